// round 14
// baseline (speedup 1.0000x reference)
#include <cuda_runtime.h>
#include <math.h>
#include <stdint.h>

#define S_LEN 2048
#define DM    2048
#define QH    32
#define KVH   8
#define DH    64
#define KV_W  (2 * KVH * DH)   // 1024

// ---------------- scratch (allocation-free: __device__ globals) ----------------
__device__ float g_Qf[S_LEN * DM];            // fp32 Q proj (pre-rope)
__device__ float g_KVf[S_LEN * KV_W];         // fp32 KV proj
__device__ uint2 g_Qp[S_LEN * DM / 2];        // packed rope'd scaled Q
__device__ uint2 g_Kp[S_LEN * KVH * DH / 2];  // packed rope'd K
__device__ uint2 g_Vtp[KVH * DH * S_LEN / 2]; // packed V^T (pairs along seq)
__device__ float g_attn[S_LEN * DM];          // fp32 attention output

// ============================ helpers ====================================
__device__ __forceinline__ uint32_t smem_u32(const void* p) {
    uint32_t a;
    asm("{ .reg .u64 t; cvta.to.shared.u64 t, %1; cvt.u32.u64 %0, t; }" : "=r"(a) : "l"(p));
    return a;
}
#define CP_ASYNC16(dst, src) \
    asm volatile("cp.async.cg.shared.global [%0], [%1], 16;" :: "r"(dst), "l"(src))
#define CP_COMMIT() asm volatile("cp.async.commit_group;" ::: "memory")
#define CP_WAIT1()  asm volatile("cp.async.wait_group 1;" ::: "memory")
#define CP_WAIT0()  asm volatile("cp.async.wait_group 0;" ::: "memory")

__device__ __forceinline__ uint32_t pack_bf16(float f1_hi, float f0_lo) {
    uint32_t d;
    asm("cvt.rn.bf16x2.f32 %0, %1, %2;" : "=r"(d) : "f"(f1_hi), "f"(f0_lo));
    return d;
}
// round-to-nearest hi/lo split of a pair: f = hi + lo, |lo| <= 2^-8 |f|
__device__ __forceinline__ void split2(float f0, float f1, uint32_t& h, uint32_t& l) {
    h = pack_bf16(f1, f0);
    float h0 = __uint_as_float(h << 16);
    float h1 = __uint_as_float(h & 0xFFFF0000u);
    l = pack_bf16(f1 - h1, f0 - h0);
}
__device__ __forceinline__ void mma_bf16(float* d,
                                         uint32_t a0, uint32_t a1, uint32_t a2, uint32_t a3,
                                         uint32_t b0, uint32_t b1) {
    asm volatile(
        "mma.sync.aligned.m16n8k16.row.col.f32.bf16.bf16.f32 "
        "{%0,%1,%2,%3}, {%4,%5,%6,%7}, {%8,%9}, {%0,%1,%2,%3};"
        : "+f"(d[0]), "+f"(d[1]), "+f"(d[2]), "+f"(d[3])
        : "r"(a0), "r"(a1), "r"(a2), "r"(a3), "r"(b0), "r"(b1));
}

// ==============================================================================
// 3xBF16 GEMM (R8/R13 structure; MMA loops reordered term-outer so 8
// independent MMAs sit between same-accumulator reuses — bit-identical order
// per accumulator: hh, hl, lh).
// ==============================================================================
#define BK     16
#define SSTR   24
#define ST_F   (128 * SSTR)
#define STG_F  (2 * ST_F)
#define NSTG   3
#define TG_SMEM (NSTG * STG_F * 4)  // 73728 B

__global__ __launch_bounds__(128, 2)
void tgemm_bf16_nt_bias(const float* __restrict__ A, const float* __restrict__ B,
                        const float* __restrict__ bias, float* __restrict__ C,
                        int M, int N, int K)
{
    extern __shared__ float sm[];
    const uint32_t smb = smem_u32(sm);

    const int tid  = threadIdx.x;
    const int wid  = tid >> 5;
    const int lane = tid & 31;
    const int qr   = lane >> 2;
    const int qc   = lane & 3;
    const int wm   = (wid & 1) * 64;
    const int wn   = (wid >> 1) * 64;
    const int brow = blockIdx.y * 128;
    const int bcol = blockIdx.x * 128;

    const float* Ag = A + (size_t)(brow + tid) * K;
    const float* Bg = B + (size_t)(bcol + tid) * K;
    const uint32_t dst_off = (uint32_t)(tid * SSTR) * 4;

    const int NT = K / BK;

    auto issue_stage = [&](int kt) {
        const uint32_t da = smb + (uint32_t)((kt % NSTG) * STG_F) * 4 + dst_off;
        const uint32_t db = da + ST_F * 4;
        const float* sa = Ag + kt * BK;
        const float* sb = Bg + kt * BK;
#pragma unroll
        for (int j = 0; j < 4; j++) {
            CP_ASYNC16(da + 16 * j, sa + 4 * j);
            CP_ASYNC16(db + 16 * j, sb + 4 * j);
        }
    };

    float acc[4][8][4];
#pragma unroll
    for (int mt = 0; mt < 4; mt++)
#pragma unroll
        for (int nt = 0; nt < 8; nt++)
#pragma unroll
            for (int i = 0; i < 4; i++) acc[mt][nt][i] = 0.0f;

    issue_stage(0); CP_COMMIT();
    issue_stage(1); CP_COMMIT();

    for (int kt = 0; kt < NT; kt++) {
        CP_WAIT1();
        __syncthreads();

        if (kt + 2 < NT) issue_stage(kt + 2);
        CP_COMMIT();

        const float* As = sm + (kt % NSTG) * STG_F;
        const float* Bs = As + ST_F;

        uint32_t bh[8][2], bl[8][2];
#pragma unroll
        for (int nt = 0; nt < 8; nt++) {
            const int off = (wn + nt * 8 + qr) * SSTR + 2 * qc;
            float2 f = *(const float2*)&Bs[off];
            float2 g = *(const float2*)&Bs[off + 8];
            split2(f.x, f.y, bh[nt][0], bl[nt][0]);
            split2(g.x, g.y, bh[nt][1], bl[nt][1]);
        }
#pragma unroll
        for (int mt = 0; mt < 4; mt++) {
            const int off = (wm + mt * 16 + qr) * SSTR + 2 * qc;
            float2 f0 = *(const float2*)&As[off];
            float2 f1 = *(const float2*)&As[off + 8 * SSTR];
            float2 f2 = *(const float2*)&As[off + 8];
            float2 f3 = *(const float2*)&As[off + 8 * SSTR + 8];
            uint32_t ah0, ah1, ah2, ah3, al0, al1, al2, al3;
            split2(f0.x, f0.y, ah0, al0);
            split2(f1.x, f1.y, ah1, al1);
            split2(f2.x, f2.y, ah2, al2);
            split2(f3.x, f3.y, ah3, al3);
            // term-outer: 8 independent MMAs between same-acc reuse
#pragma unroll
            for (int nt = 0; nt < 8; nt++)
                mma_bf16(acc[mt][nt], ah0, ah1, ah2, ah3, bh[nt][0], bh[nt][1]);
#pragma unroll
            for (int nt = 0; nt < 8; nt++)
                mma_bf16(acc[mt][nt], ah0, ah1, ah2, ah3, bl[nt][0], bl[nt][1]);
#pragma unroll
            for (int nt = 0; nt < 8; nt++)
                mma_bf16(acc[mt][nt], al0, al1, al2, al3, bh[nt][0], bh[nt][1]);
        }
        __syncthreads();
    }

#pragma unroll
    for (int mt = 0; mt < 4; mt++) {
        const int row = brow + wm + mt * 16 + qr;
#pragma unroll
        for (int nt = 0; nt < 8; nt++) {
            const int col = bcol + wn + nt * 8 + qc * 2;
            const float b0 = bias[col], b1 = bias[col + 1];
            *(float2*)(C + (size_t)row * N + col) =
                make_float2(acc[mt][nt][0] + b0, acc[mt][nt][1] + b1);
            *(float2*)(C + (size_t)(row + 8) * N + col) =
                make_float2(acc[mt][nt][2] + b0, acc[mt][nt][3] + b1);
        }
    }
}

// ==============================================================================
// RoPE + scale + pack (freq table per-block; 32 double-pows per block)
// ==============================================================================
__global__ void ropepack_kernel(const float* __restrict__ X, uint2* __restrict__ out,
                                int H, int istride, int ostride, float scale)
{
    __shared__ float sfreq[32];
    if (threadIdx.x < 32)
        sfreq[threadIdx.x] = (float)pow(10000.0, -(double)threadIdx.x / 32.0);
    __syncthreads();

    int idx = blockIdx.x * blockDim.x + threadIdx.x;
    int total = S_LEN * H * (DH / 2);
    if (idx >= total) return;

    int j = idx & 31;
    int t = idx >> 5;
    int h = t % H;
    int s = t / H;

    float theta = (float)s * sfreq[j];
    float sn, cs;
    sincosf(theta, &sn, &cs);

    const float* p = X + (size_t)s * istride + h * DH + 2 * j;
    float x1 = p[0], x2 = p[1];
    float o1 = (x1 * cs - x2 * sn) * scale;
    float o2 = (x1 * sn + x2 * cs) * scale;
    uint2 o;
    split2(o1, o2, o.x, o.y);
    out[(size_t)s * ostride + h * (DH / 2) + j] = o;
}

// V^T pack: g_Vtp[hk*64+d][sp] = split(V[2sp][hk,d], V[2sp+1][hk,d])
__global__ void vtpack_kernel(const float* __restrict__ KV, uint2* __restrict__ Vt)
{
    int idx = blockIdx.x * blockDim.x + threadIdx.x;
    if (idx >= KVH * DH * (S_LEN / 2)) return;
    int sp = idx & (S_LEN / 2 - 1);
    int d  = (idx >> 10) & (DH - 1);
    int hk = idx >> 16;
    const float* base = KV + (size_t)(2 * sp) * KV_W + KVH * DH + hk * DH + d;
    float v0 = base[0];
    float v1 = base[KV_W];
    uint2 o;
    split2(v0, v1, o.x, o.y);
    Vt[idx] = o;
}

// ==============================================================================
// Flash attention: all operands pre-packed; K and V^T cp.async double-buffered;
// P fragments in registers (R13-proven); MMA loops term-outer (bit-identical).
// Block = (128 q-rows, head), 128 threads = 4 warps; warp owns 32 rows.
// smem: QHL 36864 + K 2x18432 + V 2x18432 = 110592 B -> occ 2.
// ==============================================================================
#define AST 36                                   // uint2 row stride
#define KBUF_B (64 * AST * 8)                    // 18432 B per K/V buffer
#define OFF_K  36864                             // after QHL (128*36*8)
#define OFF_V  (OFF_K + 2 * KBUF_B)              // 73728
#define FA_SMEM (OFF_V + 2 * KBUF_B)             // 110592

__global__ __launch_bounds__(128, 2)
void flash_attn_pk(const uint2* __restrict__ Qp, const uint2* __restrict__ Kp,
                   const uint2* __restrict__ Vtp, float* __restrict__ O)
{
    extern __shared__ char smc[];
    const uint32_t smb = smem_u32(smc);
    uint2* QHL = (uint2*)smc;

    const int qt   = blockIdx.x;
    const int h    = blockIdx.y;
    const int hk   = h >> 2;
    const int tid  = threadIdx.x;
    const int wid  = tid >> 5;
    const int lane = tid & 31;
    const int qr   = lane >> 2;
    const int qc   = lane & 3;
    const int wm   = wid * 32;

    // loader mapping: thread owns row (tid>>1), 16-uint2 half (tid&1)
    const int lrow  = tid >> 1;
    const int lhalf = tid & 1;
    const uint2* kg0 = Kp + (size_t)lrow * (KVH * DH / 2) + hk * (DH / 2) + lhalf * 16;
    const uint2* vg0 = Vtp + (size_t)(hk * 64 + lrow) * (S_LEN / 2) + lhalf * 16;
    const uint32_t ldst = (uint32_t)(lrow * AST + lhalf * 16) * 8;

    auto issue_KV = [&](int kt) {
        const uint2* ks = kg0 + (size_t)(kt * 64) * (KVH * DH / 2);
        const uint2* vs = vg0 + kt * 32;
        uint32_t kd = smb + OFF_K + (uint32_t)((kt & 1) * KBUF_B) + ldst;
        uint32_t vd = smb + OFF_V + (uint32_t)((kt & 1) * KBUF_B) + ldst;
#pragma unroll
        for (int j = 0; j < 8; j++) {
            CP_ASYNC16(kd + 16 * j, ks + 2 * j);
            CP_ASYNC16(vd + 16 * j, vs + 2 * j);
        }
    };

    // prologue: tile 0 in flight; Q tile copied (packed, pure copy)
    issue_KV(0); CP_COMMIT();
    {
        const uint2* src = Qp + (size_t)(qt * 128 + tid) * (DM / 2) + h * (DH / 2);
        uint2* dst = QHL + tid * AST;
#pragma unroll
        for (int j = 0; j < 16; j++)
            *(uint4*)(dst + 2 * j) = *(const uint4*)(src + 2 * j);
    }

    float m_i[2][2], l_i[2][2];
#pragma unroll
    for (int mt = 0; mt < 2; mt++)
#pragma unroll
        for (int hf = 0; hf < 2; hf++) { m_i[mt][hf] = -1e30f; l_i[mt][hf] = 0.0f; }

    float acc[2][8][4];
#pragma unroll
    for (int mt = 0; mt < 2; mt++)
#pragma unroll
        for (int nt = 0; nt < 8; nt++)
#pragma unroll
            for (int i = 0; i < 4; i++) acc[mt][nt][i] = 0.0f;

    for (int kt = 0; kt < 32; kt++) {
        __syncthreads();   // all warps done reading buffers of tile kt-1
        if (kt + 1 < 32) { issue_KV(kt + 1); CP_COMMIT(); CP_WAIT1(); }
        else             { CP_WAIT0(); }
        __syncthreads();   // tile kt visible to all

        const uint2* Kcur = (const uint2*)(smc + OFF_K + (kt & 1) * KBUF_B);
        const uint2* Vcur = (const uint2*)(smc + OFF_V + (kt & 1) * KBUF_B);

        // ---- S = Q @ K^T (3xBF16, term-outer) ----
        float s[2][8][4];
#pragma unroll
        for (int mt = 0; mt < 2; mt++)
#pragma unroll
            for (int nt = 0; nt < 8; nt++)
#pragma unroll
                for (int i = 0; i < 4; i++) s[mt][nt][i] = 0.0f;

#pragma unroll
        for (int ks = 0; ks < 4; ks++) {
            uint2 bk[8][2];
#pragma unroll
            for (int nt = 0; nt < 8; nt++) {
                const int o = (nt * 8 + qr) * AST + ks * 8 + qc;
                bk[nt][0] = Kcur[o];
                bk[nt][1] = Kcur[o + 4];
            }
#pragma unroll
            for (int mt = 0; mt < 2; mt++) {
                const int qb = (wm + mt * 16 + qr) * AST + ks * 8 + qc;
                uint2 a0 = QHL[qb];
                uint2 a1 = QHL[qb + 8 * AST];
                uint2 a2 = QHL[qb + 4];
                uint2 a3 = QHL[qb + 8 * AST + 4];
#pragma unroll
                for (int nt = 0; nt < 8; nt++)
                    mma_bf16(s[mt][nt], a0.x, a1.x, a2.x, a3.x, bk[nt][0].x, bk[nt][1].x);
#pragma unroll
                for (int nt = 0; nt < 8; nt++)
                    mma_bf16(s[mt][nt], a0.x, a1.x, a2.x, a3.x, bk[nt][0].y, bk[nt][1].y);
#pragma unroll
                for (int nt = 0; nt < 8; nt++)
                    mma_bf16(s[mt][nt], a0.y, a1.y, a2.y, a3.y, bk[nt][0].x, bk[nt][1].x);
            }
        }

        // ---- online softmax (R13 exact) ----
#pragma unroll
        for (int mt = 0; mt < 2; mt++) {
#pragma unroll
            for (int hf = 0; hf < 2; hf++) {
                float mx = -1e30f;
#pragma unroll
                for (int nt = 0; nt < 8; nt++)
                    mx = fmaxf(mx, fmaxf(s[mt][nt][2 * hf], s[mt][nt][2 * hf + 1]));
                mx = fmaxf(mx, __shfl_xor_sync(0xffffffffu, mx, 1));
                mx = fmaxf(mx, __shfl_xor_sync(0xffffffffu, mx, 2));
                float m_new = fmaxf(m_i[mt][hf], mx);
                float alpha = __expf(m_i[mt][hf] - m_new);
                float rs = 0.0f;
#pragma unroll
                for (int nt = 0; nt < 8; nt++) {
                    s[mt][nt][2 * hf]     = __expf(s[mt][nt][2 * hf] - m_new);
                    s[mt][nt][2 * hf + 1] = __expf(s[mt][nt][2 * hf + 1] - m_new);
                    rs += s[mt][nt][2 * hf] + s[mt][nt][2 * hf + 1];
                }
                rs += __shfl_xor_sync(0xffffffffu, rs, 1);
                rs += __shfl_xor_sync(0xffffffffu, rs, 2);
                l_i[mt][hf] = l_i[mt][hf] * alpha + rs;
                m_i[mt][hf] = m_new;
#pragma unroll
                for (int nt = 0; nt < 8; nt++) {
                    acc[mt][nt][2 * hf]     *= alpha;
                    acc[mt][nt][2 * hf + 1] *= alpha;
                }
            }
        }

        // ---- acc += P @ V: P frags in registers, V^T pre-packed (LDS.64) ----
#pragma unroll
        for (int ks = 0; ks < 4; ks++) {
            uint2 bv[8][2];
#pragma unroll
            for (int nt = 0; nt < 8; nt++) {
                const int o = (nt * 8 + qr) * AST + ks * 8 + qc;
                bv[nt][0] = Vcur[o];
                bv[nt][1] = Vcur[o + 4];
            }
#pragma unroll
            for (int mt = 0; mt < 2; mt++) {
                uint32_t ph0, pl0, ph1, pl1, ph2, pl2, ph3, pl3;
                split2(s[mt][2 * ks][0],     s[mt][2 * ks][1],     ph0, pl0);
                split2(s[mt][2 * ks][2],     s[mt][2 * ks][3],     ph1, pl1);
                split2(s[mt][2 * ks + 1][0], s[mt][2 * ks + 1][1], ph2, pl2);
                split2(s[mt][2 * ks + 1][2], s[mt][2 * ks + 1][3], ph3, pl3);
#pragma unroll
                for (int nt = 0; nt < 8; nt++)
                    mma_bf16(acc[mt][nt], ph0, ph1, ph2, ph3, bv[nt][0].x, bv[nt][1].x);
#pragma unroll
                for (int nt = 0; nt < 8; nt++)
                    mma_bf16(acc[mt][nt], ph0, ph1, ph2, ph3, bv[nt][0].y, bv[nt][1].y);
#pragma unroll
                for (int nt = 0; nt < 8; nt++)
                    mma_bf16(acc[mt][nt], pl0, pl1, pl2, pl3, bv[nt][0].x, bv[nt][1].x);
            }
        }
    }

    // ---- epilogue: normalize, store fp32 ----
#pragma unroll
    for (int mt = 0; mt < 2; mt++) {
        const float i0 = 1.0f / l_i[mt][0];
        const float i1 = 1.0f / l_i[mt][1];
        float* d0 = O + (size_t)(qt * 128 + wm + mt * 16 + qr) * DM + h * DH;
        float* d1 = d0 + (size_t)8 * DM;
#pragma unroll
        for (int nt = 0; nt < 8; nt++) {
            *(float2*)(d0 + nt * 8 + 2 * qc) =
                make_float2(acc[mt][nt][0] * i0, acc[mt][nt][1] * i0);
            *(float2*)(d1 + nt * 8 + 2 * qc) =
                make_float2(acc[mt][nt][2] * i1, acc[mt][nt][3] * i1);
        }
    }
}

// ==============================================================================
// launch
// ==============================================================================
extern "C" void kernel_launch(void* const* d_in, const int* in_sizes, int n_in,
                              void* d_out, int out_size)
{
    const float* x     = (const float*)d_in[0];
    const float* W_q   = (const float*)d_in[1];
    const float* b_q   = (const float*)d_in[2];
    const float* W_kv  = (const float*)d_in[3];
    const float* b_kv  = (const float*)d_in[4];
    const float* W_out = (const float*)d_in[5];
    const float* b_out = (const float*)d_in[6];
    float* out = (float*)d_out;

    float *qf, *kvf, *abuf;
    uint2 *qp, *kp, *vtp;
    cudaGetSymbolAddress((void**)&qf,   g_Qf);
    cudaGetSymbolAddress((void**)&kvf,  g_KVf);
    cudaGetSymbolAddress((void**)&qp,   g_Qp);
    cudaGetSymbolAddress((void**)&kp,   g_Kp);
    cudaGetSymbolAddress((void**)&vtp,  g_Vtp);
    cudaGetSymbolAddress((void**)&abuf, g_attn);

    cudaFuncSetAttribute(flash_attn_pk, cudaFuncAttributeMaxDynamicSharedMemorySize, FA_SMEM);
    cudaFuncSetAttribute(tgemm_bf16_nt_bias, cudaFuncAttributeMaxDynamicSharedMemorySize, TG_SMEM);

    // projections (fp32 out)
    tgemm_bf16_nt_bias<<<dim3(DM / 128, S_LEN / 128), 128, TG_SMEM>>>(
        x, W_q, b_q, qf, S_LEN, DM, DM);
    tgemm_bf16_nt_bias<<<dim3(KV_W / 128, S_LEN / 128), 128, TG_SMEM>>>(
        x, W_kv, b_kv, kvf, S_LEN, KV_W, DM);

    // rope+scale+pack Q ; rope+pack K ; transpose+pack V
    ropepack_kernel<<<(S_LEN * QH * 32 + 255) / 256, 256>>>(qf, qp, QH, DM, DM / 2, 0.125f);
    ropepack_kernel<<<(S_LEN * KVH * 32 + 255) / 256, 256>>>(kvf, kp, KVH, KV_W, KVH * DH / 2, 1.0f);
    vtpack_kernel<<<(KVH * DH * S_LEN / 2 + 255) / 256, 256>>>(kvf, vtp);

    // flash attention (packed operands, double-buffered cp.async K/V)
    flash_attn_pk<<<dim3(S_LEN / 128, QH), 128, FA_SMEM>>>(qp, kp, vtp, abuf);

    // output projection
    tgemm_bf16_nt_bias<<<dim3(DM / 128, S_LEN / 128), 128, TG_SMEM>>>(
        abuf, W_out, b_out, out, S_LEN, DM, DM);
}